// round 3
// baseline (speedup 1.0000x reference)
#include <cuda_runtime.h>
#include <cstdint>

// DigitCaps fused single kernel, round 3: pack-over-b f32x2, 6 blocks/SM.
// B=128, J=4608, INPUT_D=8, D=8, M=4, C=10, N=J*M=18432.
// Grid = 2304 blocks x 128 threads. Block owns JT=2 j's; thread owns
// 1 j x 2 b's (8 votes). f32x2 lanes = the two b's (natural reg pairs).

#define J_TOTAL 4608
#define JT 2
#define TPB 128
#define NB (J_TOTAL / JT)
#define WJ 528      // padded floats per j of duplicated W (512 used)
#define ASTR 84     // padded floats per seg slice (80 used)
#define NSLICE 64   // 2-way shared slices

__device__ float g_S[1024];     // S[b*8+d]
__device__ float g_seg[80];     // winner-gated sums [c*8+d]
__device__ float g_cnt[16];     // winner counts [c]
__device__ unsigned g_ticket;

typedef unsigned long long u64;

static __device__ __forceinline__ u64 pack2(float lo, float hi) {
    u64 r;
    asm("mov.b64 %0, {%1, %2};"
        : "=l"(r) : "r"(__float_as_uint(lo)), "r"(__float_as_uint(hi)));
    return r;
}
static __device__ __forceinline__ void unpack2(u64 v, float& lo, float& hi) {
    unsigned a, b;
    asm("mov.b64 {%0, %1}, %2;" : "=r"(a), "=r"(b) : "l"(v));
    lo = __uint_as_float(a); hi = __uint_as_float(b);
}
static __device__ __forceinline__ u64 fma2(u64 a, u64 b, u64 c) {
    u64 d;
    asm("fma.rn.f32x2 %0, %1, %2, %3;" : "=l"(d) : "l"(a), "l"(b), "l"(c));
    return d;
}
static __device__ __forceinline__ u64 mul2(u64 a, u64 b) {
    u64 d;
    asm("mul.rn.f32x2 %0, %1, %2;" : "=l"(d) : "l"(a), "l"(b));
    return d;
}
static __device__ __forceinline__ u64 add2(u64 a, u64 b) {
    u64 d;
    asm("add.rn.f32x2 %0, %1, %2;" : "=l"(d) : "l"(a), "l"(b));
    return d;
}
static __device__ __forceinline__ u64 shfl_xor64(u64 v, int m) {
    return (u64)__shfl_xor_sync(0xFFFFFFFFu, v, m);
}

__global__ __launch_bounds__(TPB, 6) void caps_kernel(
    const float* __restrict__ x,    // [B, J, 8]
    const float* __restrict__ Wg,   // [J, 8, 32]
    const float* __restrict__ dc,   // [10, 8]
    float* __restrict__ out, int out_size)
{
    __shared__ float Wsh[JT * WJ];          //  4224 B  (W duplicated {w,w})
    __shared__ float acc[NSLICE * ASTR];    // 21504 B  (2-way shared seg slices)
    __shared__ float dcd[160];              //   640 B  (dc duplicated {v,v})
    __shared__ float dcn[80];
    __shared__ unsigned s_last;

    const int t  = threadIdx.x;
    const int tj = t & 1;        // j within block
    const int bg = t >> 1;       // b-pair index: b0=2*bg, b1=2*bg+1
    const int j  = blockIdx.x * JT + tj;

    // ---- W tile load, duplicated: Wsh[j][k]{w,w}, k = i*32 + (m*8+d) ----
    {
        const float4* src = reinterpret_cast<const float4*>(Wg)
                          + (size_t)blockIdx.x * (JT * 64);
        float4 v = src[t];                 // 512 floats total, 1 float4/thread
        int jj  = t >> 6;
        int rem = (t & 63) * 4;
        float* dst = &Wsh[jj * WJ + rem * 2];
        reinterpret_cast<u64*>(dst)[0] = pack2(v.x, v.x);
        reinterpret_cast<u64*>(dst)[1] = pack2(v.y, v.y);
        reinterpret_cast<u64*>(dst)[2] = pack2(v.z, v.z);
        reinterpret_cast<u64*>(dst)[3] = pack2(v.w, v.w);
    }
    if (t < 80) {
        float v = dc[t];
        reinterpret_cast<u64*>(&dcd[t * 2])[0] = pack2(v, v);
    }
    float* myslice = &acc[bg * ASTR];
    if (tj == 0) {
        #pragma unroll
        for (int q = 0; q < 21; q++)
            reinterpret_cast<float4*>(myslice)[q] = make_float4(0.f, 0.f, 0.f, 0.f);
    }
    __syncthreads();

    // ---- x: pack {x_b0[i], x_b1[i]} ----
    u64 xd[8];
    {
        const float4* xp0 = reinterpret_cast<const float4*>(
            x + ((size_t)(bg * 2)     * J_TOTAL + j) * 8);
        const float4* xp1 = reinterpret_cast<const float4*>(
            x + ((size_t)(bg * 2 + 1) * J_TOTAL + j) * 8);
        float4 a0 = xp0[0], a1 = xp0[1];
        float4 b0 = xp1[0], b1 = xp1[1];
        xd[0] = pack2(a0.x, b0.x); xd[1] = pack2(a0.y, b0.y);
        xd[2] = pack2(a0.z, b0.z); xd[3] = pack2(a0.w, b0.w);
        xd[4] = pack2(a1.x, b1.x); xd[5] = pack2(a1.y, b1.y);
        xd[6] = pack2(a1.z, b1.z); xd[7] = pack2(a1.w, b1.w);
    }

    u64 sreg2[8];
    #pragma unroll
    for (int d = 0; d < 8; d++) sreg2[d] = 0ull;
    u64 cnt64 = 0ull;

    const float* wbase = &Wsh[tj * WJ];

    #pragma unroll
    for (int m = 0; m < 4; m++) {
        // ---- u2[d] = {u_b0[d], u_b1[d]} ----
        u64 u2[8];
        #pragma unroll
        for (int d = 0; d < 8; d++) u2[d] = 0ull;
        #pragma unroll
        for (int i = 0; i < 8; i++) {
            const ulonglong2* wp = reinterpret_cast<const ulonglong2*>(
                wbase + (i * 32 + m * 8) * 2);
            ulonglong2 wA = wp[0], wB = wp[1], wC = wp[2], wD = wp[3];
            u2[0] = fma2(xd[i], wA.x, u2[0]);
            u2[1] = fma2(xd[i], wA.y, u2[1]);
            u2[2] = fma2(xd[i], wB.x, u2[2]);
            u2[3] = fma2(xd[i], wB.y, u2[3]);
            u2[4] = fma2(xd[i], wC.x, u2[4]);
            u2[5] = fma2(xd[i], wC.y, u2[5]);
            u2[6] = fma2(xd[i], wD.x, u2[6]);
            u2[7] = fma2(xd[i], wD.y, u2[7]);
        }
        #pragma unroll
        for (int d = 0; d < 8; d++) sreg2[d] = add2(sreg2[d], u2[d]);

        // ---- argmax_c: sims in packed lanes (one per b), scalar compare ----
        float best0 = -3.402823466e38f, best1 = -3.402823466e38f;
        int bc0 = 0, bc1 = 0;
        #pragma unroll
        for (int c = 0; c < 10; c++) {
            const ulonglong2* dpp = reinterpret_cast<const ulonglong2*>(&dcd[c * 16]);
            ulonglong2 dA = dpp[0], dB = dpp[1], dC = dpp[2], dD = dpp[3];
            u64 s2 = mul2(u2[0], dA.x);
            s2 = fma2(u2[1], dA.y, s2);
            s2 = fma2(u2[2], dB.x, s2);
            s2 = fma2(u2[3], dB.y, s2);
            s2 = fma2(u2[4], dC.x, s2);
            s2 = fma2(u2[5], dC.y, s2);
            s2 = fma2(u2[6], dD.x, s2);
            s2 = fma2(u2[7], dD.y, s2);
            float s0, s1; unpack2(s2, s0, s1);
            if (s0 > best0) { best0 = s0; bc0 = c; }
            if (s1 > best1) { best1 = s1; bc1 = c; }
        }
        cnt64 += (1ull << (bc0 * 6)) + (1ull << (bc1 * 6));

        // ---- winner-gated scatter, 2-way shared slice, phase by tj ----
        float ul[8], uh[8];
        #pragma unroll
        for (int d = 0; d < 8; d++) unpack2(u2[d], ul[d], uh[d]);
        #pragma unroll
        for (int ph = 0; ph < 2; ph++) {
            if (tj == ph) {
                float* p0 = myslice + bc0 * 8;
                float4 a0 = *reinterpret_cast<float4*>(p0);
                float4 a1 = *reinterpret_cast<float4*>(p0 + 4);
                a0.x += ul[0]; a0.y += ul[1]; a0.z += ul[2]; a0.w += ul[3];
                a1.x += ul[4]; a1.y += ul[5]; a1.z += ul[6]; a1.w += ul[7];
                *reinterpret_cast<float4*>(p0)     = a0;
                *reinterpret_cast<float4*>(p0 + 4) = a1;
                float* p1 = myslice + bc1 * 8;
                float4 c0 = *reinterpret_cast<float4*>(p1);
                float4 c1 = *reinterpret_cast<float4*>(p1 + 4);
                c0.x += uh[0]; c0.y += uh[1]; c0.z += uh[2]; c0.w += uh[3];
                c1.x += uh[4]; c1.y += uh[5]; c1.z += uh[6]; c1.w += uh[7];
                *reinterpret_cast<float4*>(p1)     = c0;
                *reinterpret_cast<float4*>(p1 + 4) = c1;
            }
            __syncwarp();
        }
    }

    // ---- S: combine the two j-lanes (t ^ 1 shares the same b-pair) ----
    #pragma unroll
    for (int d = 0; d < 8; d++) {
        u64 v = add2(sreg2[d], shfl_xor64(sreg2[d], 1));
        if (tj == 0) {
            float lo, hi; unpack2(v, lo, hi);
            atomicAdd(&g_S[(bg * 2)     * 8 + d], lo);
            atomicAdd(&g_S[(bg * 2 + 1) * 8 + d], hi);
        }
    }

    // ---- counts: warp REDUX per class ----
    {
        int lane = t & 31;
        #pragma unroll
        for (int c = 0; c < 10; c++) {
            unsigned v = (unsigned)((cnt64 >> (6 * c)) & 63ull);
            unsigned s = __reduce_add_sync(0xFFFFFFFFu, v);
            if (lane == 0) atomicAdd(&g_cnt[c], (float)s);
        }
    }

    __syncthreads();
    // ---- block-reduce the 64 seg slices ----
    if (t < 80) {
        float s0 = 0.f, s1 = 0.f, s2 = 0.f, s3 = 0.f;
        #pragma unroll 4
        for (int r = 0; r < NSLICE; r += 4) {
            s0 += acc[(r + 0) * ASTR + t];
            s1 += acc[(r + 1) * ASTR + t];
            s2 += acc[(r + 2) * ASTR + t];
            s3 += acc[(r + 3) * ASTR + t];
        }
        atomicAdd(&g_seg[t], (s0 + s1) + (s2 + s3));
    }

    // ---- last-block finish + reset (graph-replay determinism) ----
    __threadfence();
    __syncthreads();
    if (t == 0) s_last = (atomicAdd(&g_ticket, 1u) == (unsigned)(NB - 1)) ? 1u : 0u;
    __syncthreads();
    if (!s_last) return;

    if (t < 80) {
        int c = t >> 3;
        float d0  = dc[t];
        float seg = __ldcg(&g_seg[t]);
        float cnt = __ldcg(&g_cnt[c]);
        float v = d0 + (seg - cnt * d0) * (1.0f / 2359296.0f);  // /(B*N)
        dcn[t] = v;
        if (out_size >= 1360) out[1280 + t] = v;
        if (out_size == 80)   out[t] = v;
    }
    __syncthreads();
    if (out_size >= 1280) {
        float sv[8];
        #pragma unroll
        for (int d = 0; d < 8; d++) sv[d] = __ldcg(&g_S[t * 8 + d]);
        #pragma unroll
        for (int c = 0; c < 10; c++) {
            float s = 0.f;
            #pragma unroll
            for (int d = 0; d < 8; d++) s = fmaf(sv[d], dcn[c * 8 + d], s);
            out[t * 10 + c] = s * (1.0f / 18432.0f);
        }
    }
    #pragma unroll
    for (int d = 0; d < 8; d++) g_S[t * 8 + d] = 0.f;
    if (t < 80) g_seg[t] = 0.f;
    if (t < 16) g_cnt[t] = 0.f;
    if (t == 0) g_ticket = 0u;
}

extern "C" void kernel_launch(void* const* d_in, const int* in_sizes, int n_in,
                              void* d_out, int out_size)
{
    // x = 128*4608*8 = 4718592, W = 4608*8*32 = 1179648, dc = 80.
    const float* x  = nullptr;
    const float* W  = nullptr;
    const float* dc = nullptr;
    for (int i = 0; i < n_in; i++) {
        if (in_sizes[i] == 4718592)      x  = (const float*)d_in[i];
        else if (in_sizes[i] == 1179648) W  = (const float*)d_in[i];
        else if (in_sizes[i] == 80)      dc = (const float*)d_in[i];
    }
    if (!x)  x  = (const float*)d_in[0];
    if (!W)  W  = (const float*)d_in[1];
    if (!dc) dc = (const float*)d_in[2];

    caps_kernel<<<NB, TPB>>>(x, W, dc, (float*)d_out, out_size);
}

// round 5
// speedup vs baseline: 1.8747x; 1.8747x over previous
#include <cuda_runtime.h>
#include <cstdint>

// DigitCaps, round 5: round-4 design with s_kernel fixed (W stride was j*512
// instead of j*256 -> OOB crash; WS duplication made both f32x2 lanes compute
// the same d). caps_kernel: JT=4, BT=4, private seg slices, scalar x, 5 blk/SM.
// B=128, J=4608, INPUT_D=8, D=8, M=4, C=10, N=J*M=18432.

#define J_TOTAL 4608
#define JT 4
#define TPB 128
#define NB (J_TOTAL / JT)
#define WSTR 264   // padded floats per j-row of W in smem
#define ASTR 84    // padded per-thread seg-slice stride (80 used)

#define SJT 16     // j's per block in s_kernel
#define SNB (J_TOTAL / SJT)

__device__ float g_S[1024];     // S[b*8+d] = sum_n u[b,n,d]
__device__ float g_seg[80];     // winner-gated sums [c*8+d]
__device__ float g_cnt[16];     // winner counts [c]
__device__ unsigned g_ticket;

typedef unsigned long long u64;

static __device__ __forceinline__ u64 pack2(float lo, float hi) {
    u64 r;
    asm("mov.b64 %0, {%1, %2};"
        : "=l"(r) : "r"(__float_as_uint(lo)), "r"(__float_as_uint(hi)));
    return r;
}
static __device__ __forceinline__ void unpack2(u64 v, float& lo, float& hi) {
    unsigned a, b;
    asm("mov.b64 {%0, %1}, %2;" : "=r"(a), "=r"(b) : "l"(v));
    lo = __uint_as_float(a); hi = __uint_as_float(b);
}
static __device__ __forceinline__ u64 fma2(u64 a, u64 b, u64 c) {
    u64 d;
    asm("fma.rn.f32x2 %0, %1, %2, %3;" : "=l"(d) : "l"(a), "l"(b), "l"(c));
    return d;
}
static __device__ __forceinline__ u64 mul2(u64 a, u64 b) {
    u64 d;
    asm("mul.rn.f32x2 %0, %1, %2;" : "=l"(d) : "l"(a), "l"(b));
    return d;
}
static __device__ __forceinline__ u64 add2(u64 a, u64 b) {
    u64 d;
    asm("add.rn.f32x2 %0, %1, %2;" : "=l"(d) : "l"(a), "l"(b));
    return d;
}

// ---------------------------------------------------------------------------
// s_kernel: S[b,d] = sum_{j,i} x[b,j,i] * WS[j,i,d],  WS[j,i,d] = sum_m W[j,i,m*8+d]
// Grid 288 x 128. Block owns SJT=16 j's; thread owns one b.
// wsd is PLAIN (not duplicated): u64 pairs are {d0,d1},{d2,d3},{d4,d5},{d6,d7}.
// ---------------------------------------------------------------------------
__global__ __launch_bounds__(TPB) void s_kernel(
    const float* __restrict__ x, const float* __restrict__ Wg)
{
    __shared__ float wsd[SJT * 64];   // 4 KB: WS[jj][i*8+d]
    const int t = threadIdx.x;
    const int jbase = blockIdx.x * SJT;

    // WS: 1024 entries, 8 per thread. W[j][i][k] at j*256 + i*32 + k.
    for (int e = t; e < SJT * 64; e += TPB) {
        int jj = e >> 6, k = e & 63, i = k >> 3, d = k & 7;
        const float* wp = Wg + (size_t)(jbase + jj) * 256 + i * 32 + d;
        wsd[e] = (wp[0] + wp[8]) + (wp[16] + wp[24]);
    }
    __syncthreads();

    u64 acc[4];   // {S_d0,S_d1},{S_d2,S_d3},{S_d4,S_d5},{S_d6,S_d7}
    #pragma unroll
    for (int p = 0; p < 4; p++) acc[p] = 0ull;

    const float* xrow = x + ((size_t)t * J_TOTAL + jbase) * 8;
    #pragma unroll 4
    for (int jj = 0; jj < SJT; jj++) {
        const float4* xp = reinterpret_cast<const float4*>(xrow + jj * 8);
        float4 a = xp[0], b = xp[1];
        float xs[8] = {a.x, a.y, a.z, a.w, b.x, b.y, b.z, b.w};
        #pragma unroll
        for (int i = 0; i < 8; i++) {
            u64 xx = pack2(xs[i], xs[i]);
            const ulonglong2* wp = reinterpret_cast<const ulonglong2*>(
                &wsd[jj * 64 + i * 8]);           // uniform addr -> broadcast
            ulonglong2 wA = wp[0], wB = wp[1];    // 8 plain floats = 4 d-pairs
            acc[0] = fma2(xx, wA.x, acc[0]);
            acc[1] = fma2(xx, wA.y, acc[1]);
            acc[2] = fma2(xx, wB.x, acc[2]);
            acc[3] = fma2(xx, wB.y, acc[3]);
        }
    }
    #pragma unroll
    for (int p = 0; p < 4; p++) {
        float lo, hi; unpack2(acc[p], lo, hi);
        atomicAdd(&g_S[t * 8 + p * 2],     lo);
        atomicAdd(&g_S[t * 8 + p * 2 + 1], hi);
    }
}

// ---------------------------------------------------------------------------
// caps_kernel: u + argmax + winner-gated seg/cnt; last block finishes + resets.
// ---------------------------------------------------------------------------
__global__ __launch_bounds__(TPB, 5) void caps_kernel(
    const float* __restrict__ x,    // [B, J, 8]
    const float* __restrict__ Wg,   // [J, 8, 32]
    const float* __restrict__ dc,   // [10, 8]
    float* __restrict__ out, int out_size)
{
    __shared__ float Wsh[JT * WSTR];     //  4224 B
    __shared__ float acc[TPB * ASTR];    // 43008 B: per-thread seg slices
    __shared__ float dcsh[80];
    __shared__ float dcn[80];
    __shared__ unsigned s_last;

    const int t  = threadIdx.x;
    const int tj = t & 3;       // j within block
    const int bg = t >> 2;      // b-group (32 groups x 4 b)
    const int j  = blockIdx.x * JT + tj;

    // ---- cooperative W tile load (padded rows) ----
    {
        const float4* src = reinterpret_cast<const float4*>(Wg)
                          + (size_t)blockIdx.x * (JT * 64);
        #pragma unroll
        for (int r = 0; r < 2; r++) {
            int g = t + r * TPB, jj = g >> 6, rem = g & 63;
            *reinterpret_cast<float4*>(&Wsh[jj * WSTR + rem * 4]) = src[g];
        }
    }
    if (t < 80) dcsh[t] = dc[t];
    float* myacc = &acc[t * ASTR];
    #pragma unroll
    for (int q = 0; q < 21; q++)
        reinterpret_cast<float4*>(myacc)[q] = make_float4(0.f, 0.f, 0.f, 0.f);
    __syncthreads();

    // ---- x for my 4 b's, scalar (32 regs) ----
    float xv[4][8];
    #pragma unroll
    for (int bb = 0; bb < 4; bb++) {
        const float4* xp = reinterpret_cast<const float4*>(
            x + ((size_t)(bg * 4 + bb) * J_TOTAL + j) * 8);
        float4 a = xp[0], b = xp[1];
        xv[bb][0]=a.x; xv[bb][1]=a.y; xv[bb][2]=a.z; xv[bb][3]=a.w;
        xv[bb][4]=b.x; xv[bb][5]=b.y; xv[bb][6]=b.z; xv[bb][7]=b.w;
    }

    u64 cnt64 = 0ull;

    #pragma unroll
    for (int m = 0; m < 4; m++) {
        // ---- u2[bb][p] = packed pair {u[2p], u[2p+1]} over d ----
        u64 u2[4][4];
        #pragma unroll
        for (int bb = 0; bb < 4; bb++)
            #pragma unroll
            for (int p = 0; p < 4; p++) u2[bb][p] = 0ull;
        #pragma unroll
        for (int i = 0; i < 8; i++) {
            const ulonglong2* wp = reinterpret_cast<const ulonglong2*>(
                &Wsh[tj * WSTR + i * 32 + m * 8]);
            ulonglong2 wA = wp[0], wB = wp[1];
            #pragma unroll
            for (int bb = 0; bb < 4; bb++) {
                u64 xx = pack2(xv[bb][i], xv[bb][i]);   // alu-pipe mov
                u2[bb][0] = fma2(xx, wA.x, u2[bb][0]);
                u2[bb][1] = fma2(xx, wA.y, u2[bb][1]);
                u2[bb][2] = fma2(xx, wB.x, u2[bb][2]);
                u2[bb][3] = fma2(xx, wB.y, u2[bb][3]);
            }
        }

        // ---- argmax_c <u, dc[c]> (strict >, first max) ----
        float best[4]; int bc[4];
        #pragma unroll
        for (int bb = 0; bb < 4; bb++) { best[bb] = -3.402823466e38f; bc[bb] = 0; }
        #pragma unroll
        for (int c = 0; c < 10; c++) {
            const ulonglong2* dpp = reinterpret_cast<const ulonglong2*>(&dcsh[c * 8]);
            ulonglong2 dA = dpp[0], dB = dpp[1];
            #pragma unroll
            for (int bb = 0; bb < 4; bb++) {
                u64 s2 = mul2(u2[bb][0], dA.x);
                s2 = fma2(u2[bb][1], dA.y, s2);
                s2 = fma2(u2[bb][2], dB.x, s2);
                s2 = fma2(u2[bb][3], dB.y, s2);
                float lo, hi; unpack2(s2, lo, hi);
                float s = lo + hi;
                if (s > best[bb]) { best[bb] = s; bc[bb] = c; }
            }
        }

        // ---- winner-gated accumulation into private slice (packed adds) ----
        #pragma unroll
        for (int bb = 0; bb < 4; bb++) {
            cnt64 += 1ull << (bc[bb] * 6);
            ulonglong2* p2 = reinterpret_cast<ulonglong2*>(myacc + bc[bb] * 8);
            ulonglong2 a0 = p2[0], a1 = p2[1];
            a0.x = add2(a0.x, u2[bb][0]); a0.y = add2(a0.y, u2[bb][1]);
            a1.x = add2(a1.x, u2[bb][2]); a1.y = add2(a1.y, u2[bb][3]);
            p2[0] = a0; p2[1] = a1;
        }
    }

    // ---- counts: warp REDUX per class ----
    {
        int lane = t & 31;
        #pragma unroll
        for (int c = 0; c < 10; c++) {
            unsigned v = (unsigned)((cnt64 >> (6 * c)) & 63ull);
            unsigned s = __reduce_add_sync(0xFFFFFFFFu, v);
            if (lane == 0) atomicAdd(&g_cnt[c], (float)s);
        }
    }

    __syncthreads();
    // ---- block-reduce the 128 seg slices ----
    if (t < 80) {
        float s0 = 0.f, s1 = 0.f, s2 = 0.f, s3 = 0.f;
        #pragma unroll 4
        for (int r = 0; r < TPB; r += 4) {
            s0 += acc[(r + 0) * ASTR + t];
            s1 += acc[(r + 1) * ASTR + t];
            s2 += acc[(r + 2) * ASTR + t];
            s3 += acc[(r + 3) * ASTR + t];
        }
        atomicAdd(&g_seg[t], (s0 + s1) + (s2 + s3));
    }

    // ---- last-block finish + reset (graph-replay determinism) ----
    __threadfence();
    __syncthreads();
    if (t == 0) s_last = (atomicAdd(&g_ticket, 1u) == (unsigned)(NB - 1)) ? 1u : 0u;
    __syncthreads();
    if (!s_last) return;

    if (t < 80) {
        int c = t >> 3;
        float d0  = dc[t];
        float seg = __ldcg(&g_seg[t]);
        float cnt = __ldcg(&g_cnt[c]);
        float v = d0 + (seg - cnt * d0) * (1.0f / 2359296.0f);  // /(B*N)
        dcn[t] = v;
        if (out_size >= 1360) out[1280 + t] = v;
        if (out_size == 80)   out[t] = v;
    }
    __syncthreads();
    if (out_size >= 1280) {
        float sv[8];
        #pragma unroll
        for (int d = 0; d < 8; d++) sv[d] = __ldcg(&g_S[t * 8 + d]);
        #pragma unroll
        for (int c = 0; c < 10; c++) {
            float s = 0.f;
            #pragma unroll
            for (int d = 0; d < 8; d++) s = fmaf(sv[d], dcn[c * 8 + d], s);
            out[t * 10 + c] = s * (1.0f / 18432.0f);
        }
    }
    // reset accumulators for the next graph replay
    #pragma unroll
    for (int d = 0; d < 8; d++) g_S[t * 8 + d] = 0.f;
    if (t < 80) g_seg[t] = 0.f;
    if (t < 16) g_cnt[t] = 0.f;
    if (t == 0) g_ticket = 0u;
}

extern "C" void kernel_launch(void* const* d_in, const int* in_sizes, int n_in,
                              void* d_out, int out_size)
{
    // x = 128*4608*8 = 4718592, W = 4608*8*32 = 1179648, dc = 80.
    const float* x  = nullptr;
    const float* W  = nullptr;
    const float* dc = nullptr;
    for (int i = 0; i < n_in; i++) {
        if (in_sizes[i] == 4718592)      x  = (const float*)d_in[i];
        else if (in_sizes[i] == 1179648) W  = (const float*)d_in[i];
        else if (in_sizes[i] == 80)      dc = (const float*)d_in[i];
    }
    if (!x)  x  = (const float*)d_in[0];
    if (!W)  W  = (const float*)d_in[1];
    if (!dc) dc = (const float*)d_in[2];

    s_kernel<<<SNB, TPB>>>(x, W);
    caps_kernel<<<NB, TPB>>>(x, W, dc, (float*)d_out, out_size);
}